// round 1
// baseline (speedup 1.0000x reference)
#include <cuda_runtime.h>

#define TT 2048
#define DD 1024
#define HH 16
#define HSZ 64
#define DFF 4096

// ---------------- scratch (no allocs allowed) ----------------
__device__ float g_h[TT * DD];          // LN output (reused for LN1 and LN2)
__device__ float g_wpack[DD * 3 * DD];  // packed [D, 3D] QKV weights
__device__ float g_qkv[TT * 3 * DD];    // QKV activations [T, 3D]
__device__ float g_att[TT * DD];        // attention output (head-concat) [T, D]
__device__ float g_x2[TT * DD];         // residual after attention
__device__ float g_ff[TT * DFF];        // FFN hidden

// ---------------- LayerNorm: one block per row ----------------
__global__ __launch_bounds__(256) void ln_kernel(
    const float* __restrict__ x, const float* __restrict__ g,
    const float* __restrict__ b, float* __restrict__ y)
{
    int row = blockIdx.x;
    int tid = threadIdx.x;
    float4 v = reinterpret_cast<const float4*>(x + (size_t)row * DD)[tid];
    float s  = v.x + v.y + v.z + v.w;
    float ss = v.x * v.x + v.y * v.y + v.z * v.z + v.w * v.w;
    #pragma unroll
    for (int o = 16; o > 0; o >>= 1) {
        s  += __shfl_xor_sync(0xffffffffu, s, o);
        ss += __shfl_xor_sync(0xffffffffu, ss, o);
    }
    __shared__ float sb[8], ssb[8], stats[2];
    int wid = tid >> 5, lane = tid & 31;
    if (lane == 0) { sb[wid] = s; ssb[wid] = ss; }
    __syncthreads();
    if (tid == 0) {
        float a = 0.f, c = 0.f;
        #pragma unroll
        for (int i = 0; i < 8; i++) { a += sb[i]; c += ssb[i]; }
        float mean = a * (1.0f / DD);
        float var  = c * (1.0f / DD) - mean * mean;
        stats[0] = mean;
        stats[1] = rsqrtf(var + 1e-6f);
    }
    __syncthreads();
    float mean = stats[0], rstd = stats[1];
    float4 gg = reinterpret_cast<const float4*>(g)[tid];
    float4 bb = reinterpret_cast<const float4*>(b)[tid];
    float4 o;
    o.x = (v.x - mean) * rstd * gg.x + bb.x;
    o.y = (v.y - mean) * rstd * gg.y + bb.y;
    o.z = (v.z - mean) * rstd * gg.z + bb.z;
    o.w = (v.w - mean) * rstd * gg.w + bb.w;
    reinterpret_cast<float4*>(y + (size_t)row * DD)[tid] = o;
}

// ---------------- pack Wq/Wk/Wv [H,D,HS] -> [D, 3D] ----------------
__global__ __launch_bounds__(256) void pack_qkv(
    const float* __restrict__ Wq, const float* __restrict__ Wk,
    const float* __restrict__ Wv, float* __restrict__ P)
{
    int idx = blockIdx.x * 256 + threadIdx.x;
    if (idx >= DD * 3 * DD) return;
    int d = idx / (3 * DD);
    int c = idx % (3 * DD);
    const float* W = (c < DD) ? Wq : (c < 2 * DD ? Wk : Wv);
    int cc = c & (DD - 1);
    int h  = cc >> 6;
    int hs = cc & 63;
    P[idx] = W[(size_t)h * DD * HSZ + (size_t)d * HSZ + hs];
}

// ---------------- SGEMM 128x128x8, 256 threads, 8x8 per thread ----------------
// C[M,N] = epi( A[M,K] * B[K,N] )
// EPI: 0 = none, 1 = +bias[col] +resid[row,col], 2 = relu(+bias[col])
template <int EPI>
__global__ __launch_bounds__(256) void sgemm128(
    int M, int N, int K,
    const float* __restrict__ A, const float* __restrict__ B,
    const float* __restrict__ bias, const float* __restrict__ resid,
    float* __restrict__ C)
{
    __shared__ float As[8][132];   // transposed A tile, padded
    __shared__ float Bs[8][128];

    int tid  = threadIdx.x;
    int bcol = blockIdx.x, brow = blockIdx.y;
    int trow = tid >> 4;         // 0..15
    int tcol = tid & 15;         // 0..15

    int aRow = tid >> 1;         // 0..127
    int aCol = (tid & 1) * 4;    // 0 or 4
    int bRow = tid >> 5;         // 0..7
    int bCol = (tid & 31) * 4;   // 0..124

    const float* Ab = A + (size_t)(brow * 128) * K;
    const float* Bb = B + bcol * 128;

    float acc[8][8];
    #pragma unroll
    for (int i = 0; i < 8; i++)
        #pragma unroll
        for (int j = 0; j < 8; j++) acc[i][j] = 0.f;

    for (int k0 = 0; k0 < K; k0 += 8) {
        float4 av = *reinterpret_cast<const float4*>(Ab + (size_t)aRow * K + k0 + aCol);
        As[aCol + 0][aRow] = av.x;
        As[aCol + 1][aRow] = av.y;
        As[aCol + 2][aRow] = av.z;
        As[aCol + 3][aRow] = av.w;
        float4 bv = *reinterpret_cast<const float4*>(Bb + (size_t)(k0 + bRow) * N + bCol);
        *reinterpret_cast<float4*>(&Bs[bRow][bCol]) = bv;
        __syncthreads();

        #pragma unroll
        for (int k = 0; k < 8; ++k) {
            float rm[8], rn[8];
            float4 m0 = *reinterpret_cast<const float4*>(&As[k][trow * 8]);
            float4 m1 = *reinterpret_cast<const float4*>(&As[k][trow * 8 + 4]);
            rm[0]=m0.x; rm[1]=m0.y; rm[2]=m0.z; rm[3]=m0.w;
            rm[4]=m1.x; rm[5]=m1.y; rm[6]=m1.z; rm[7]=m1.w;
            float4 n0 = *reinterpret_cast<const float4*>(&Bs[k][tcol * 8]);
            float4 n1 = *reinterpret_cast<const float4*>(&Bs[k][tcol * 8 + 4]);
            rn[0]=n0.x; rn[1]=n0.y; rn[2]=n0.z; rn[3]=n0.w;
            rn[4]=n1.x; rn[5]=n1.y; rn[6]=n1.z; rn[7]=n1.w;
            #pragma unroll
            for (int i = 0; i < 8; i++)
                #pragma unroll
                for (int j = 0; j < 8; j++)
                    acc[i][j] += rm[i] * rn[j];
        }
        __syncthreads();
    }

    // epilogue
    int colBase = bcol * 128 + tcol * 8;
    #pragma unroll
    for (int i = 0; i < 8; i++) {
        int row = brow * 128 + trow * 8 + i;
        float* Crow = C + (size_t)row * N + colBase;
        #pragma unroll
        for (int jj = 0; jj < 2; jj++) {
            float4 o;
            o.x = acc[i][jj * 4 + 0];
            o.y = acc[i][jj * 4 + 1];
            o.z = acc[i][jj * 4 + 2];
            o.w = acc[i][jj * 4 + 3];
            if constexpr (EPI >= 1) {
                float4 bv = *reinterpret_cast<const float4*>(bias + colBase + jj * 4);
                o.x += bv.x; o.y += bv.y; o.z += bv.z; o.w += bv.w;
            }
            if constexpr (EPI == 1) {
                float4 rv = *reinterpret_cast<const float4*>(resid + (size_t)row * N + colBase + jj * 4);
                o.x += rv.x; o.y += rv.y; o.z += rv.z; o.w += rv.w;
            }
            if constexpr (EPI == 2) {
                o.x = fmaxf(o.x, 0.f); o.y = fmaxf(o.y, 0.f);
                o.z = fmaxf(o.z, 0.f); o.w = fmaxf(o.w, 0.f);
            }
            *reinterpret_cast<float4*>(Crow + jj * 4) = o;
        }
    }
}

// ---------------- flash attention: 64-query x 32-key tiles ----------------
// qkv: [T, 3D], q at col h*64, k at D + h*64, v at 2D + h*64
// out: [T, D] head-concat
__global__ __launch_bounds__(128) void flash_attn_kernel(
    const float* __restrict__ qkv, float* __restrict__ out)
{
    __shared__ float Qs[64][65];
    __shared__ float Ks[32][65];
    __shared__ float Vs[32][65];
    __shared__ float Ps[64][33];

    int tid = threadIdx.x;
    int ty  = tid >> 3;   // 0..15 -> 4 query rows each
    int tx  = tid & 7;    // 0..7
    int qb  = blockIdx.x; // 0..31 (64-row query block)
    int h   = blockIdx.y;

    const float* qp = qkv + h * HSZ;
    const float* kp = qkv + DD + h * HSZ;
    const float* vp = qkv + 2 * DD + h * HSZ;

    // load Q tile [64][64]
    for (int i = tid; i < 64 * 64; i += 128) {
        int r = i >> 6, d = i & 63;
        Qs[r][d] = qp[(size_t)(qb * 64 + r) * (3 * DD) + d];
    }

    float m[4], l[4], O[4][8];
    #pragma unroll
    for (int r = 0; r < 4; r++) {
        m[r] = -1e30f; l[r] = 0.f;
        #pragma unroll
        for (int c = 0; c < 8; c++) O[r][c] = 0.f;
    }

    const float scale = 0.125f;  // 1/sqrt(64)
    int nkb = qb * 2 + 2;
    int trow0 = qb * 64 + ty * 4;

    for (int kb = 0; kb < nkb; ++kb) {
        __syncthreads();
        for (int i = tid; i < 32 * 64; i += 128) {
            int r = i >> 6, d = i & 63;
            Ks[r][d] = kp[(size_t)(kb * 32 + r) * (3 * DD) + d];
            Vs[r][d] = vp[(size_t)(kb * 32 + r) * (3 * DD) + d];
        }
        __syncthreads();

        // S = Q K^T  (4x4 per thread)
        float s[4][4];
        #pragma unroll
        for (int r = 0; r < 4; r++)
            #pragma unroll
            for (int c = 0; c < 4; c++) s[r][c] = 0.f;
        #pragma unroll 8
        for (int d = 0; d < 64; ++d) {
            float qr[4], kc[4];
            #pragma unroll
            for (int r = 0; r < 4; r++) qr[r] = Qs[ty * 4 + r][d];
            #pragma unroll
            for (int c = 0; c < 4; c++) kc[c] = Ks[tx * 4 + c][d];
            #pragma unroll
            for (int r = 0; r < 4; r++)
                #pragma unroll
                for (int c = 0; c < 4; c++)
                    s[r][c] += qr[r] * kc[c];
        }

        // scale + causal mask + row max
        int scol0 = kb * 32 + tx * 4;
        float mb[4];
        #pragma unroll
        for (int r = 0; r < 4; r++) {
            mb[r] = -1e30f;
            #pragma unroll
            for (int c = 0; c < 4; c++) {
                float v = s[r][c] * scale;
                if (scol0 + c > trow0 + r) v = -1e30f;
                s[r][c] = v;
                mb[r] = fmaxf(mb[r], v);
            }
        }
        #pragma unroll
        for (int r = 0; r < 4; r++) {
            #pragma unroll
            for (int o = 1; o < 8; o <<= 1)
                mb[r] = fmaxf(mb[r], __shfl_xor_sync(0xffffffffu, mb[r], o));
        }

        // online softmax update
        float psum[4];
        #pragma unroll
        for (int r = 0; r < 4; r++) {
            float mn = fmaxf(m[r], mb[r]);
            float alpha = __expf(m[r] - mn);
            m[r] = mn;
            float rs = 0.f;
            #pragma unroll
            for (int c = 0; c < 4; c++) {
                float p = __expf(s[r][c] - mn);
                s[r][c] = p;
                rs += p;
            }
            psum[r] = rs;
            l[r] *= alpha;
            #pragma unroll
            for (int c = 0; c < 8; c++) O[r][c] *= alpha;
        }
        #pragma unroll
        for (int r = 0; r < 4; r++) {
            #pragma unroll
            for (int o = 1; o < 8; o <<= 1)
                psum[r] += __shfl_xor_sync(0xffffffffu, psum[r], o);
            l[r] += psum[r];
        }

        // stage P
        #pragma unroll
        for (int r = 0; r < 4; r++)
            #pragma unroll
            for (int c = 0; c < 4; c++)
                Ps[ty * 4 + r][tx * 4 + c] = s[r][c];
        __syncthreads();

        // O += P V
        #pragma unroll 8
        for (int si = 0; si < 32; ++si) {
            float pr[4], vv[8];
            #pragma unroll
            for (int r = 0; r < 4; r++) pr[r] = Ps[ty * 4 + r][si];
            #pragma unroll
            for (int c = 0; c < 8; c++) vv[c] = Vs[si][c * 8 + tx];
            #pragma unroll
            for (int r = 0; r < 4; r++)
                #pragma unroll
                for (int c = 0; c < 8; c++)
                    O[r][c] += pr[r] * vv[c];
        }
    }

    // normalize + write
    #pragma unroll
    for (int r = 0; r < 4; r++) {
        float inv = 1.0f / l[r];
        int t = qb * 64 + ty * 4 + r;
        #pragma unroll
        for (int c = 0; c < 8; c++)
            out[(size_t)t * DD + h * HSZ + c * 8 + tx] = O[r][c] * inv;
    }
}

// ---------------- launch ----------------
extern "C" void kernel_launch(void* const* d_in, const int* in_sizes, int n_in,
                              void* d_out, int out_size)
{
    const float* x    = (const float*)d_in[0];
    const float* Wq   = (const float*)d_in[1];
    const float* Wk   = (const float*)d_in[2];
    const float* Wv   = (const float*)d_in[3];
    const float* Wo   = (const float*)d_in[4];
    const float* bo   = (const float*)d_in[5];
    const float* W1   = (const float*)d_in[6];
    const float* b1   = (const float*)d_in[7];
    const float* W2   = (const float*)d_in[8];
    const float* b2   = (const float*)d_in[9];
    const float* ln1s = (const float*)d_in[10];
    const float* ln1b = (const float*)d_in[11];
    const float* ln2s = (const float*)d_in[12];
    const float* ln2b = (const float*)d_in[13];
    float* out = (float*)d_out;

    float *h, *wp, *qkv, *att, *x2, *ff;
    cudaGetSymbolAddress((void**)&h,   g_h);
    cudaGetSymbolAddress((void**)&wp,  g_wpack);
    cudaGetSymbolAddress((void**)&qkv, g_qkv);
    cudaGetSymbolAddress((void**)&att, g_att);
    cudaGetSymbolAddress((void**)&x2,  g_x2);
    cudaGetSymbolAddress((void**)&ff,  g_ff);

    // 1. LN1
    ln_kernel<<<TT, 256>>>(x, ln1s, ln1b, h);
    // 2. pack QKV weights -> [D, 3D]
    pack_qkv<<<(DD * 3 * DD + 255) / 256, 256>>>(Wq, Wk, Wv, wp);
    // 3. QKV GEMM: [T,D] x [D,3D] -> [T,3D]
    sgemm128<0><<<dim3(3 * DD / 128, TT / 128), 256>>>(TT, 3 * DD, DD, h, wp,
                                                       nullptr, nullptr, qkv);
    // 4. causal flash attention -> [T,D]
    flash_attn_kernel<<<dim3(TT / 64, HH), 128>>>(qkv, att);
    // 5. output proj + bias + residual: x2 = x + att*Wo + bo
    sgemm128<1><<<dim3(DD / 128, TT / 128), 256>>>(TT, DD, DD, att, Wo, bo, x, x2);
    // 6. LN2
    ln_kernel<<<TT, 256>>>(x2, ln2s, ln2b, h);
    // 7. FFN1: relu(h*W1 + b1)
    sgemm128<2><<<dim3(DFF / 128, TT / 128), 256>>>(TT, DFF, DD, h, W1, b1,
                                                    nullptr, ff);
    // 8. FFN2: out = x2 + ff*W2 + b2
    sgemm128<1><<<dim3(DD / 128, TT / 128), 256>>>(TT, DD, DFF, ff, W2, b2, x2, out);
}

// round 2
// speedup vs baseline: 2.1321x; 2.1321x over previous
#include <cuda_runtime.h>
#include <cstdint>

#define TT 2048
#define DD 1024
#define HH 16
#define HSZ 64
#define DFF 4096

// ---------------- scratch (no allocs allowed) ----------------
__device__ float g_h[TT * DD];          // LN output (reused for LN1 and LN2)
__device__ float g_wpack[DD * 3 * DD];  // packed [D, 3D] QKV weights
__device__ float g_qkv[TT * 3 * DD];    // QKV activations [T, 3D]
__device__ float g_att[TT * DD];        // attention output (head-concat) [T, D]
__device__ float g_x2[TT * DD];         // residual after attention
__device__ float g_ff[TT * DFF];        // FFN hidden

// ---------------- LayerNorm: one block per row ----------------
__global__ __launch_bounds__(256) void ln_kernel(
    const float* __restrict__ x, const float* __restrict__ g,
    const float* __restrict__ b, float* __restrict__ y)
{
    int row = blockIdx.x;
    int tid = threadIdx.x;
    float4 v = reinterpret_cast<const float4*>(x + (size_t)row * DD)[tid];
    float s  = v.x + v.y + v.z + v.w;
    float ss = v.x * v.x + v.y * v.y + v.z * v.z + v.w * v.w;
    #pragma unroll
    for (int o = 16; o > 0; o >>= 1) {
        s  += __shfl_xor_sync(0xffffffffu, s, o);
        ss += __shfl_xor_sync(0xffffffffu, ss, o);
    }
    __shared__ float sb[8], ssb[8], stats[2];
    int wid = tid >> 5, lane = tid & 31;
    if (lane == 0) { sb[wid] = s; ssb[wid] = ss; }
    __syncthreads();
    if (tid == 0) {
        float a = 0.f, c = 0.f;
        #pragma unroll
        for (int i = 0; i < 8; i++) { a += sb[i]; c += ssb[i]; }
        float mean = a * (1.0f / DD);
        float var  = c * (1.0f / DD) - mean * mean;
        stats[0] = mean;
        stats[1] = rsqrtf(var + 1e-6f);
    }
    __syncthreads();
    float mean = stats[0], rstd = stats[1];
    float4 gg = reinterpret_cast<const float4*>(g)[tid];
    float4 bb = reinterpret_cast<const float4*>(b)[tid];
    float4 o;
    o.x = (v.x - mean) * rstd * gg.x + bb.x;
    o.y = (v.y - mean) * rstd * gg.y + bb.y;
    o.z = (v.z - mean) * rstd * gg.z + bb.z;
    o.w = (v.w - mean) * rstd * gg.w + bb.w;
    reinterpret_cast<float4*>(y + (size_t)row * DD)[tid] = o;
}

// ---------------- pack Wq/Wk/Wv [H,D,HS] -> [D, 3D] ----------------
__global__ __launch_bounds__(256) void pack_qkv(
    const float* __restrict__ Wq, const float* __restrict__ Wk,
    const float* __restrict__ Wv, float* __restrict__ P)
{
    int idx = blockIdx.x * 256 + threadIdx.x;
    if (idx >= DD * 3 * DD) return;
    int d = idx / (3 * DD);
    int c = idx % (3 * DD);
    const float* W = (c < DD) ? Wq : (c < 2 * DD ? Wk : Wv);
    int cc = c & (DD - 1);
    int h  = cc >> 6;
    int hs = cc & 63;
    P[idx] = W[(size_t)h * DD * HSZ + (size_t)d * HSZ + hs];
}

// ---------------- tf32 helpers ----------------
__device__ __forceinline__ float f2tf32(float x) {
    uint32_t r;
    asm("cvt.rna.tf32.f32 %0, %1;" : "=r"(r) : "f"(x));
    return __uint_as_float(r);
}

__device__ __forceinline__ void mma_tf32(
    float& d0, float& d1, float& d2, float& d3,
    uint32_t a0, uint32_t a1, uint32_t a2, uint32_t a3,
    uint32_t b0, uint32_t b1)
{
    asm volatile(
        "mma.sync.aligned.m16n8k8.row.col.f32.tf32.tf32.f32 "
        "{%0,%1,%2,%3}, {%4,%5,%6,%7}, {%8,%9}, {%0,%1,%2,%3};\n"
        : "+f"(d0), "+f"(d1), "+f"(d2), "+f"(d3)
        : "r"(a0), "r"(a1), "r"(a2), "r"(a3), "r"(b0), "r"(b1));
}

// ---------------- tf32 tensor-core GEMM ----------------
// Block tile 128x128, BK=16, 256 threads = 8 warps (2x4), warp tile 64x32.
// C[M,N] = epi( A[M,K] * B[K,N] )
// EPI: 0 = none, 1 = +bias[col] +resid[row,col], 2 = relu(+bias[col])
template <int EPI>
__global__ __launch_bounds__(256) void tgemm(
    int M, int N, int K,
    const float* __restrict__ A, const float* __restrict__ B,
    const float* __restrict__ bias, const float* __restrict__ resid,
    float* __restrict__ C)
{
    __shared__ float As[2][128][20];   // [buf][row][k] padded
    __shared__ float Bs[2][16][132];   // [buf][k][col] padded

    const int tid  = threadIdx.x;
    const int bcol = blockIdx.x, brow = blockIdx.y;
    const int warp = tid >> 5;
    const int lane = tid & 31;
    const int wm = warp & 1;          // 0..1 : rows
    const int wn = warp >> 1;         // 0..3 : cols
    const int g  = lane >> 2;         // 0..7
    const int tg = lane & 3;          // 0..3

    // global load indices (2 float4 per thread per tile for A and B)
    const int aRow0 = tid >> 2, aCol0 = (tid & 3) * 4;
    const int aRow1 = (tid + 256) >> 2, aCol1 = ((tid + 256) & 3) * 4;
    const int bRow0 = tid >> 5, bCol0 = (tid & 31) * 4;
    const int bRow1 = (tid + 256) >> 5, bCol1 = ((tid + 256) & 31) * 4;

    const float* Ab = A + (size_t)(brow * 128) * K;
    const float* Bb = B + bcol * 128;

    float acc[4][4][4];
    #pragma unroll
    for (int mt = 0; mt < 4; mt++)
        #pragma unroll
        for (int nt = 0; nt < 4; nt++)
            #pragma unroll
            for (int i = 0; i < 4; i++) acc[mt][nt][i] = 0.f;

    const int KT = K >> 4;

    // prologue: tile 0 -> buf 0
    {
        float4 va0 = *reinterpret_cast<const float4*>(Ab + (size_t)aRow0 * K + aCol0);
        float4 va1 = *reinterpret_cast<const float4*>(Ab + (size_t)aRow1 * K + aCol1);
        float4 vb0 = *reinterpret_cast<const float4*>(Bb + (size_t)bRow0 * N + bCol0);
        float4 vb1 = *reinterpret_cast<const float4*>(Bb + (size_t)bRow1 * N + bCol1);
        As[0][aRow0][aCol0+0] = f2tf32(va0.x); As[0][aRow0][aCol0+1] = f2tf32(va0.y);
        As[0][aRow0][aCol0+2] = f2tf32(va0.z); As[0][aRow0][aCol0+3] = f2tf32(va0.w);
        As[0][aRow1][aCol1+0] = f2tf32(va1.x); As[0][aRow1][aCol1+1] = f2tf32(va1.y);
        As[0][aRow1][aCol1+2] = f2tf32(va1.z); As[0][aRow1][aCol1+3] = f2tf32(va1.w);
        Bs[0][bRow0][bCol0+0] = f2tf32(vb0.x); Bs[0][bRow0][bCol0+1] = f2tf32(vb0.y);
        Bs[0][bRow0][bCol0+2] = f2tf32(vb0.z); Bs[0][bRow0][bCol0+3] = f2tf32(vb0.w);
        Bs[0][bRow1][bCol1+0] = f2tf32(vb1.x); Bs[0][bRow1][bCol1+1] = f2tf32(vb1.y);
        Bs[0][bRow1][bCol1+2] = f2tf32(vb1.z); Bs[0][bRow1][bCol1+3] = f2tf32(vb1.w);
    }
    __syncthreads();

    for (int kt = 0; kt < KT; ++kt) {
        const int p = kt & 1;
        float4 va0, va1, vb0, vb1;
        if (kt + 1 < KT) {
            const int k0 = (kt + 1) << 4;
            va0 = *reinterpret_cast<const float4*>(Ab + (size_t)aRow0 * K + k0 + aCol0);
            va1 = *reinterpret_cast<const float4*>(Ab + (size_t)aRow1 * K + k0 + aCol1);
            vb0 = *reinterpret_cast<const float4*>(Bb + (size_t)(k0 + bRow0) * N + bCol0);
            vb1 = *reinterpret_cast<const float4*>(Bb + (size_t)(k0 + bRow1) * N + bCol1);
        }

        #pragma unroll
        for (int ks = 0; ks < 2; ++ks) {
            const int kk = ks * 8;
            uint32_t af[4][4], bf[4][2];
            #pragma unroll
            for (int mt = 0; mt < 4; mt++) {
                const int rm = wm * 64 + mt * 16;
                af[mt][0] = __float_as_uint(As[p][rm + g][kk + tg]);
                af[mt][1] = __float_as_uint(As[p][rm + g + 8][kk + tg]);
                af[mt][2] = __float_as_uint(As[p][rm + g][kk + tg + 4]);
                af[mt][3] = __float_as_uint(As[p][rm + g + 8][kk + tg + 4]);
            }
            #pragma unroll
            for (int nt = 0; nt < 4; nt++) {
                const int cn = wn * 32 + nt * 8;
                bf[nt][0] = __float_as_uint(Bs[p][kk + tg][cn + g]);
                bf[nt][1] = __float_as_uint(Bs[p][kk + tg + 4][cn + g]);
            }
            #pragma unroll
            for (int mt = 0; mt < 4; mt++)
                #pragma unroll
                for (int nt = 0; nt < 4; nt++)
                    mma_tf32(acc[mt][nt][0], acc[mt][nt][1],
                             acc[mt][nt][2], acc[mt][nt][3],
                             af[mt][0], af[mt][1], af[mt][2], af[mt][3],
                             bf[nt][0], bf[nt][1]);
        }

        if (kt + 1 < KT) {
            const int q = (kt + 1) & 1;
            As[q][aRow0][aCol0+0] = f2tf32(va0.x); As[q][aRow0][aCol0+1] = f2tf32(va0.y);
            As[q][aRow0][aCol0+2] = f2tf32(va0.z); As[q][aRow0][aCol0+3] = f2tf32(va0.w);
            As[q][aRow1][aCol1+0] = f2tf32(va1.x); As[q][aRow1][aCol1+1] = f2tf32(va1.y);
            As[q][aRow1][aCol1+2] = f2tf32(va1.z); As[q][aRow1][aCol1+3] = f2tf32(va1.w);
            Bs[q][bRow0][bCol0+0] = f2tf32(vb0.x); Bs[q][bRow0][bCol0+1] = f2tf32(vb0.y);
            Bs[q][bRow0][bCol0+2] = f2tf32(vb0.z); Bs[q][bRow0][bCol0+3] = f2tf32(vb0.w);
            Bs[q][bRow1][bCol1+0] = f2tf32(vb1.x); Bs[q][bRow1][bCol1+1] = f2tf32(vb1.y);
            Bs[q][bRow1][bCol1+2] = f2tf32(vb1.z); Bs[q][bRow1][bCol1+3] = f2tf32(vb1.w);
            __syncthreads();
        }
    }

    // ---------------- epilogue ----------------
    #pragma unroll
    for (int mt = 0; mt < 4; mt++) {
        const int r0 = brow * 128 + wm * 64 + mt * 16 + g;
        const int r1 = r0 + 8;
        #pragma unroll
        for (int nt = 0; nt < 4; nt++) {
            const int c = bcol * 128 + wn * 32 + nt * 8 + tg * 2;
            float2 o0 = make_float2(acc[mt][nt][0], acc[mt][nt][1]);
            float2 o1 = make_float2(acc[mt][nt][2], acc[mt][nt][3]);
            if constexpr (EPI >= 1) {
                float2 bv = *reinterpret_cast<const float2*>(bias + c);
                o0.x += bv.x; o0.y += bv.y;
                o1.x += bv.x; o1.y += bv.y;
            }
            if constexpr (EPI == 1) {
                float2 rv0 = *reinterpret_cast<const float2*>(resid + (size_t)r0 * N + c);
                float2 rv1 = *reinterpret_cast<const float2*>(resid + (size_t)r1 * N + c);
                o0.x += rv0.x; o0.y += rv0.y;
                o1.x += rv1.x; o1.y += rv1.y;
            }
            if constexpr (EPI == 2) {
                o0.x = fmaxf(o0.x, 0.f); o0.y = fmaxf(o0.y, 0.f);
                o1.x = fmaxf(o1.x, 0.f); o1.y = fmaxf(o1.y, 0.f);
            }
            *reinterpret_cast<float2*>(C + (size_t)r0 * N + c) = o0;
            *reinterpret_cast<float2*>(C + (size_t)r1 * N + c) = o1;
        }
    }
}

// ---------------- flash attention: 64-query x 32-key tiles ----------------
__global__ __launch_bounds__(128) void flash_attn_kernel(
    const float* __restrict__ qkv, float* __restrict__ out)
{
    __shared__ float Qs[64][65];
    __shared__ float Ks[32][65];
    __shared__ float Vs[32][65];
    __shared__ float Ps[64][33];

    int tid = threadIdx.x;
    int ty  = tid >> 3;   // 0..15 -> 4 query rows each
    int tx  = tid & 7;    // 0..7
    int qb  = blockIdx.x; // 0..31 (64-row query block)
    int h   = blockIdx.y;

    const float* qp = qkv + h * HSZ;
    const float* kp = qkv + DD + h * HSZ;
    const float* vp = qkv + 2 * DD + h * HSZ;

    for (int i = tid; i < 64 * 64; i += 128) {
        int r = i >> 6, d = i & 63;
        Qs[r][d] = qp[(size_t)(qb * 64 + r) * (3 * DD) + d];
    }

    float m[4], l[4], O[4][8];
    #pragma unroll
    for (int r = 0; r < 4; r++) {
        m[r] = -1e30f; l[r] = 0.f;
        #pragma unroll
        for (int c = 0; c < 8; c++) O[r][c] = 0.f;
    }

    const float scale = 0.125f;
    int nkb = qb * 2 + 2;
    int trow0 = qb * 64 + ty * 4;

    for (int kb = 0; kb < nkb; ++kb) {
        __syncthreads();
        for (int i = tid; i < 32 * 64; i += 128) {
            int r = i >> 6, d = i & 63;
            Ks[r][d] = kp[(size_t)(kb * 32 + r) * (3 * DD) + d];
            Vs[r][d] = vp[(size_t)(kb * 32 + r) * (3 * DD) + d];
        }
        __syncthreads();

        float s[4][4];
        #pragma unroll
        for (int r = 0; r < 4; r++)
            #pragma unroll
            for (int c = 0; c < 4; c++) s[r][c] = 0.f;
        #pragma unroll 8
        for (int d = 0; d < 64; ++d) {
            float qr[4], kc[4];
            #pragma unroll
            for (int r = 0; r < 4; r++) qr[r] = Qs[ty * 4 + r][d];
            #pragma unroll
            for (int c = 0; c < 4; c++) kc[c] = Ks[tx * 4 + c][d];
            #pragma unroll
            for (int r = 0; r < 4; r++)
                #pragma unroll
                for (int c = 0; c < 4; c++)
                    s[r][c] += qr[r] * kc[c];
        }

        int scol0 = kb * 32 + tx * 4;
        float mb[4];
        #pragma unroll
        for (int r = 0; r < 4; r++) {
            mb[r] = -1e30f;
            #pragma unroll
            for (int c = 0; c < 4; c++) {
                float v = s[r][c] * scale;
                if (scol0 + c > trow0 + r) v = -1e30f;
                s[r][c] = v;
                mb[r] = fmaxf(mb[r], v);
            }
        }
        #pragma unroll
        for (int r = 0; r < 4; r++) {
            #pragma unroll
            for (int o = 1; o < 8; o <<= 1)
                mb[r] = fmaxf(mb[r], __shfl_xor_sync(0xffffffffu, mb[r], o));
        }

        float psum[4];
        #pragma unroll
        for (int r = 0; r < 4; r++) {
            float mn = fmaxf(m[r], mb[r]);
            float alpha = __expf(m[r] - mn);
            m[r] = mn;
            float rs = 0.f;
            #pragma unroll
            for (int c = 0; c < 4; c++) {
                float p = __expf(s[r][c] - mn);
                s[r][c] = p;
                rs += p;
            }
            psum[r] = rs;
            l[r] *= alpha;
            #pragma unroll
            for (int c = 0; c < 8; c++) O[r][c] *= alpha;
        }
        #pragma unroll
        for (int r = 0; r < 4; r++) {
            #pragma unroll
            for (int o = 1; o < 8; o <<= 1)
                psum[r] += __shfl_xor_sync(0xffffffffu, psum[r], o);
            l[r] += psum[r];
        }

        #pragma unroll
        for (int r = 0; r < 4; r++)
            #pragma unroll
            for (int c = 0; c < 4; c++)
                Ps[ty * 4 + r][tx * 4 + c] = s[r][c];
        __syncthreads();

        #pragma unroll 8
        for (int si = 0; si < 32; ++si) {
            float pr[4], vv[8];
            #pragma unroll
            for (int r = 0; r < 4; r++) pr[r] = Ps[ty * 4 + r][si];
            #pragma unroll
            for (int c = 0; c < 8; c++) vv[c] = Vs[si][c * 8 + tx];
            #pragma unroll
            for (int r = 0; r < 4; r++)
                #pragma unroll
                for (int c = 0; c < 8; c++)
                    O[r][c] += pr[r] * vv[c];
        }
    }

    #pragma unroll
    for (int r = 0; r < 4; r++) {
        float inv = 1.0f / l[r];
        int t = qb * 64 + ty * 4 + r;
        #pragma unroll
        for (int c = 0; c < 8; c++)
            out[(size_t)t * DD + h * HSZ + c * 8 + tx] = O[r][c] * inv;
    }
}

// ---------------- launch ----------------
extern "C" void kernel_launch(void* const* d_in, const int* in_sizes, int n_in,
                              void* d_out, int out_size)
{
    const float* x    = (const float*)d_in[0];
    const float* Wq   = (const float*)d_in[1];
    const float* Wk   = (const float*)d_in[2];
    const float* Wv   = (const float*)d_in[3];
    const float* Wo   = (const float*)d_in[4];
    const float* bo   = (const float*)d_in[5];
    const float* W1   = (const float*)d_in[6];
    const float* b1   = (const float*)d_in[7];
    const float* W2   = (const float*)d_in[8];
    const float* b2   = (const float*)d_in[9];
    const float* ln1s = (const float*)d_in[10];
    const float* ln1b = (const float*)d_in[11];
    const float* ln2s = (const float*)d_in[12];
    const float* ln2b = (const float*)d_in[13];
    float* out = (float*)d_out;

    float *h, *wp, *qkv, *att, *x2, *ff;
    cudaGetSymbolAddress((void**)&h,   g_h);
    cudaGetSymbolAddress((void**)&wp,  g_wpack);
    cudaGetSymbolAddress((void**)&qkv, g_qkv);
    cudaGetSymbolAddress((void**)&att, g_att);
    cudaGetSymbolAddress((void**)&x2,  g_x2);
    cudaGetSymbolAddress((void**)&ff,  g_ff);

    // 1. LN1
    ln_kernel<<<TT, 256>>>(x, ln1s, ln1b, h);
    // 2. pack QKV weights -> [D, 3D]
    pack_qkv<<<(DD * 3 * DD + 255) / 256, 256>>>(Wq, Wk, Wv, wp);
    // 3. QKV GEMM: [T,D] x [D,3D] -> [T,3D]
    tgemm<0><<<dim3(3 * DD / 128, TT / 128), 256>>>(TT, 3 * DD, DD, h, wp,
                                                    nullptr, nullptr, qkv);
    // 4. causal flash attention -> [T,D]
    flash_attn_kernel<<<dim3(TT / 64, HH), 128>>>(qkv, att);
    // 5. output proj + bias + residual: x2 = x + att*Wo + bo
    tgemm<1><<<dim3(DD / 128, TT / 128), 256>>>(TT, DD, DD, att, Wo, bo, x, x2);
    // 6. LN2
    ln_kernel<<<TT, 256>>>(x2, ln2s, ln2b, h);
    // 7. FFN1: relu(h*W1 + b1)
    tgemm<2><<<dim3(DFF / 128, TT / 128), 256>>>(TT, DFF, DD, h, W1, b1,
                                                 nullptr, ff);
    // 8. FFN2: out = x2 + ff*W2 + b2
    tgemm<1><<<dim3(DD / 128, TT / 128), 256>>>(TT, DD, DFF, ff, W2, b2, x2, out);
}

// round 3
// speedup vs baseline: 2.7119x; 1.2720x over previous
#include <cuda_runtime.h>
#include <cstdint>

#define TT 2048
#define DD 1024
#define HH 16
#define HSZ 64
#define DFF 4096

// ---------------- scratch (no allocs allowed) ----------------
__device__ float g_h[TT * DD];          // LN output (reused for LN1 and LN2)
__device__ float g_wpack[DD * 3 * DD];  // packed [D, 3D] QKV weights
__device__ float g_qkv[TT * 3 * DD];    // QKV activations [T, 3D]
__device__ float g_att[TT * DD];        // attention output (head-concat) [T, D]
__device__ float g_x2[TT * DD];         // residual after attention
__device__ float g_ff[TT * DFF];        // FFN hidden

// ---------------- LayerNorm: one block per row ----------------
__global__ __launch_bounds__(256) void ln_kernel(
    const float* __restrict__ x, const float* __restrict__ g,
    const float* __restrict__ b, float* __restrict__ y)
{
    int row = blockIdx.x;
    int tid = threadIdx.x;
    float4 v = reinterpret_cast<const float4*>(x + (size_t)row * DD)[tid];
    float s  = v.x + v.y + v.z + v.w;
    float ss = v.x * v.x + v.y * v.y + v.z * v.z + v.w * v.w;
    #pragma unroll
    for (int o = 16; o > 0; o >>= 1) {
        s  += __shfl_xor_sync(0xffffffffu, s, o);
        ss += __shfl_xor_sync(0xffffffffu, ss, o);
    }
    __shared__ float sb[8], ssb[8], stats[2];
    int wid = tid >> 5, lane = tid & 31;
    if (lane == 0) { sb[wid] = s; ssb[wid] = ss; }
    __syncthreads();
    if (tid == 0) {
        float a = 0.f, c = 0.f;
        #pragma unroll
        for (int i = 0; i < 8; i++) { a += sb[i]; c += ssb[i]; }
        float mean = a * (1.0f / DD);
        float var  = c * (1.0f / DD) - mean * mean;
        stats[0] = mean;
        stats[1] = rsqrtf(var + 1e-6f);
    }
    __syncthreads();
    float mean = stats[0], rstd = stats[1];
    float4 gg = reinterpret_cast<const float4*>(g)[tid];
    float4 bb = reinterpret_cast<const float4*>(b)[tid];
    float4 o;
    o.x = (v.x - mean) * rstd * gg.x + bb.x;
    o.y = (v.y - mean) * rstd * gg.y + bb.y;
    o.z = (v.z - mean) * rstd * gg.z + bb.z;
    o.w = (v.w - mean) * rstd * gg.w + bb.w;
    reinterpret_cast<float4*>(y + (size_t)row * DD)[tid] = o;
}

// ---------------- pack Wq/Wk/Wv [H,D,HS] -> [D, 3D] ----------------
__global__ __launch_bounds__(256) void pack_qkv(
    const float* __restrict__ Wq, const float* __restrict__ Wk,
    const float* __restrict__ Wv, float* __restrict__ P)
{
    int idx = blockIdx.x * 256 + threadIdx.x;
    if (idx >= DD * 3 * DD) return;
    int d = idx / (3 * DD);
    int c = idx % (3 * DD);
    const float* W = (c < DD) ? Wq : (c < 2 * DD ? Wk : Wv);
    int cc = c & (DD - 1);
    int h  = cc >> 6;
    int hs = cc & 63;
    P[idx] = W[(size_t)h * DD * HSZ + (size_t)d * HSZ + hs];
}

// ---------------- tf32 helpers ----------------
__device__ __forceinline__ float f2tf32(float x) {
    uint32_t r;
    asm("cvt.rna.tf32.f32 %0, %1;" : "=r"(r) : "f"(x));
    return __uint_as_float(r);
}

__device__ __forceinline__ void mma_tf32(
    float& d0, float& d1, float& d2, float& d3,
    uint32_t a0, uint32_t a1, uint32_t a2, uint32_t a3,
    uint32_t b0, uint32_t b1)
{
    asm volatile(
        "mma.sync.aligned.m16n8k8.row.col.f32.tf32.tf32.f32 "
        "{%0,%1,%2,%3}, {%4,%5,%6,%7}, {%8,%9}, {%0,%1,%2,%3};\n"
        : "+f"(d0), "+f"(d1), "+f"(d2), "+f"(d3)
        : "r"(a0), "r"(a1), "r"(a2), "r"(a3), "r"(b0), "r"(b1));
}

// fast exp2 on the fma/alu pipes (no MUFU). valid for x <= ~0, clamped at -120.
__device__ __forceinline__ float fexp2(float x) {
    x = fmaxf(x, -120.f);
    float k  = __fadd_rn(x, 12582912.f);      // round-to-nearest integer
    int   sc = __float_as_int(k) << 23;       // integer part -> exponent bits
    float f  = __fsub_rn(x, __fsub_rn(k, 12582912.f));   // f in [-0.5, 0.5]
    float p  = 0.0013333558f;
    p = fmaf(p, f, 0.0096181291f);
    p = fmaf(p, f, 0.0555041087f);
    p = fmaf(p, f, 0.2402265070f);
    p = fmaf(p, f, 0.6931471806f);
    p = fmaf(p, f, 1.0f);
    return __int_as_float(__float_as_int(p) + sc);
}

// ---------------- tf32 tensor-core GEMM (unchanged from R2) ----------------
template <int EPI>
__global__ __launch_bounds__(256) void tgemm(
    int M, int N, int K,
    const float* __restrict__ A, const float* __restrict__ B,
    const float* __restrict__ bias, const float* __restrict__ resid,
    float* __restrict__ C)
{
    __shared__ float As[2][128][20];
    __shared__ float Bs[2][16][132];

    const int tid  = threadIdx.x;
    const int bcol = blockIdx.x, brow = blockIdx.y;
    const int warp = tid >> 5;
    const int lane = tid & 31;
    const int wm = warp & 1;
    const int wn = warp >> 1;
    const int g  = lane >> 2;
    const int tg = lane & 3;

    const int aRow0 = tid >> 2, aCol0 = (tid & 3) * 4;
    const int aRow1 = (tid + 256) >> 2, aCol1 = ((tid + 256) & 3) * 4;
    const int bRow0 = tid >> 5, bCol0 = (tid & 31) * 4;
    const int bRow1 = (tid + 256) >> 5, bCol1 = ((tid + 256) & 31) * 4;

    const float* Ab = A + (size_t)(brow * 128) * K;
    const float* Bb = B + bcol * 128;

    float acc[4][4][4];
    #pragma unroll
    for (int mt = 0; mt < 4; mt++)
        #pragma unroll
        for (int nt = 0; nt < 4; nt++)
            #pragma unroll
            for (int i = 0; i < 4; i++) acc[mt][nt][i] = 0.f;

    const int KT = K >> 4;

    {
        float4 va0 = *reinterpret_cast<const float4*>(Ab + (size_t)aRow0 * K + aCol0);
        float4 va1 = *reinterpret_cast<const float4*>(Ab + (size_t)aRow1 * K + aCol1);
        float4 vb0 = *reinterpret_cast<const float4*>(Bb + (size_t)bRow0 * N + bCol0);
        float4 vb1 = *reinterpret_cast<const float4*>(Bb + (size_t)bRow1 * N + bCol1);
        As[0][aRow0][aCol0+0] = f2tf32(va0.x); As[0][aRow0][aCol0+1] = f2tf32(va0.y);
        As[0][aRow0][aCol0+2] = f2tf32(va0.z); As[0][aRow0][aCol0+3] = f2tf32(va0.w);
        As[0][aRow1][aCol1+0] = f2tf32(va1.x); As[0][aRow1][aCol1+1] = f2tf32(va1.y);
        As[0][aRow1][aCol1+2] = f2tf32(va1.z); As[0][aRow1][aCol1+3] = f2tf32(va1.w);
        Bs[0][bRow0][bCol0+0] = f2tf32(vb0.x); Bs[0][bRow0][bCol0+1] = f2tf32(vb0.y);
        Bs[0][bRow0][bCol0+2] = f2tf32(vb0.z); Bs[0][bRow0][bCol0+3] = f2tf32(vb0.w);
        Bs[0][bRow1][bCol1+0] = f2tf32(vb1.x); Bs[0][bRow1][bCol1+1] = f2tf32(vb1.y);
        Bs[0][bRow1][bCol1+2] = f2tf32(vb1.z); Bs[0][bRow1][bCol1+3] = f2tf32(vb1.w);
    }
    __syncthreads();

    for (int kt = 0; kt < KT; ++kt) {
        const int p = kt & 1;
        float4 va0, va1, vb0, vb1;
        if (kt + 1 < KT) {
            const int k0 = (kt + 1) << 4;
            va0 = *reinterpret_cast<const float4*>(Ab + (size_t)aRow0 * K + k0 + aCol0);
            va1 = *reinterpret_cast<const float4*>(Ab + (size_t)aRow1 * K + k0 + aCol1);
            vb0 = *reinterpret_cast<const float4*>(Bb + (size_t)(k0 + bRow0) * N + bCol0);
            vb1 = *reinterpret_cast<const float4*>(Bb + (size_t)(k0 + bRow1) * N + bCol1);
        }

        #pragma unroll
        for (int ks = 0; ks < 2; ++ks) {
            const int kk = ks * 8;
            uint32_t af[4][4], bf[4][2];
            #pragma unroll
            for (int mt = 0; mt < 4; mt++) {
                const int rm = wm * 64 + mt * 16;
                af[mt][0] = __float_as_uint(As[p][rm + g][kk + tg]);
                af[mt][1] = __float_as_uint(As[p][rm + g + 8][kk + tg]);
                af[mt][2] = __float_as_uint(As[p][rm + g][kk + tg + 4]);
                af[mt][3] = __float_as_uint(As[p][rm + g + 8][kk + tg + 4]);
            }
            #pragma unroll
            for (int nt = 0; nt < 4; nt++) {
                const int cn = wn * 32 + nt * 8;
                bf[nt][0] = __float_as_uint(Bs[p][kk + tg][cn + g]);
                bf[nt][1] = __float_as_uint(Bs[p][kk + tg + 4][cn + g]);
            }
            #pragma unroll
            for (int mt = 0; mt < 4; mt++)
                #pragma unroll
                for (int nt = 0; nt < 4; nt++)
                    mma_tf32(acc[mt][nt][0], acc[mt][nt][1],
                             acc[mt][nt][2], acc[mt][nt][3],
                             af[mt][0], af[mt][1], af[mt][2], af[mt][3],
                             bf[nt][0], bf[nt][1]);
        }

        if (kt + 1 < KT) {
            const int q = (kt + 1) & 1;
            As[q][aRow0][aCol0+0] = f2tf32(va0.x); As[q][aRow0][aCol0+1] = f2tf32(va0.y);
            As[q][aRow0][aCol0+2] = f2tf32(va0.z); As[q][aRow0][aCol0+3] = f2tf32(va0.w);
            As[q][aRow1][aCol1+0] = f2tf32(va1.x); As[q][aRow1][aCol1+1] = f2tf32(va1.y);
            As[q][aRow1][aCol1+2] = f2tf32(va1.z); As[q][aRow1][aCol1+3] = f2tf32(va1.w);
            Bs[q][bRow0][bCol0+0] = f2tf32(vb0.x); Bs[q][bRow0][bCol0+1] = f2tf32(vb0.y);
            Bs[q][bRow0][bCol0+2] = f2tf32(vb0.z); Bs[q][bRow0][bCol0+3] = f2tf32(vb0.w);
            Bs[q][bRow1][bCol1+0] = f2tf32(vb1.x); Bs[q][bRow1][bCol1+1] = f2tf32(vb1.y);
            Bs[q][bRow1][bCol1+2] = f2tf32(vb1.z); Bs[q][bRow1][bCol1+3] = f2tf32(vb1.w);
            __syncthreads();
        }
    }

    #pragma unroll
    for (int mt = 0; mt < 4; mt++) {
        const int r0 = brow * 128 + wm * 64 + mt * 16 + g;
        const int r1 = r0 + 8;
        #pragma unroll
        for (int nt = 0; nt < 4; nt++) {
            const int c = bcol * 128 + wn * 32 + nt * 8 + tg * 2;
            float2 o0 = make_float2(acc[mt][nt][0], acc[mt][nt][1]);
            float2 o1 = make_float2(acc[mt][nt][2], acc[mt][nt][3]);
            if constexpr (EPI >= 1) {
                float2 bv = *reinterpret_cast<const float2*>(bias + c);
                o0.x += bv.x; o0.y += bv.y;
                o1.x += bv.x; o1.y += bv.y;
            }
            if constexpr (EPI == 1) {
                float2 rv0 = *reinterpret_cast<const float2*>(resid + (size_t)r0 * N + c);
                float2 rv1 = *reinterpret_cast<const float2*>(resid + (size_t)r1 * N + c);
                o0.x += rv0.x; o0.y += rv0.y;
                o1.x += rv1.x; o1.y += rv1.y;
            }
            if constexpr (EPI == 2) {
                o0.x = fmaxf(o0.x, 0.f); o0.y = fmaxf(o0.y, 0.f);
                o1.x = fmaxf(o1.x, 0.f); o1.y = fmaxf(o1.y, 0.f);
            }
            *reinterpret_cast<float2*>(C + (size_t)r0 * N + c) = o0;
            *reinterpret_cast<float2*>(C + (size_t)r1 * N + c) = o1;
        }
    }
}

// ---------------- tensor-core flash attention ----------------
// 128 queries x 64 keys per tile, 8 warps, one block per (qblock, head).
// smem strides chosen for conflict-free frag loads:
//   Qs,Ks,Ps: stride 68 (frag pattern row=g,col=tg)   Vs: stride 72 (row=tg,col=g)
#define QS_S 68
#define KS_S 68
#define VS_S 72
#define PS_S 68
#define FA_SMEM ((128*QS_S + 64*KS_S + 64*VS_S + 128*PS_S) * 4)

__global__ __launch_bounds__(256, 2) void flash_tc(
    const float* __restrict__ qkv, float* __restrict__ out)
{
    extern __shared__ float sm[];
    float* Qs = sm;                         // [128][68]
    float* Ks = Qs + 128 * QS_S;            // [64][68]
    float* Vs = Ks + 64 * KS_S;             // [64][72]
    float* Ps = Vs + 64 * VS_S;             // [128][68]

    const int tid  = threadIdx.x;
    const int warp = tid >> 5;
    const int lane = tid & 31;
    const int g    = lane >> 2;
    const int tg   = lane & 3;
    const int qb   = gridDim.x - 1 - blockIdx.x;   // reversed: big workloads first
    const int h    = blockIdx.y;
    const int q0   = qb * 128;
    const int w16  = warp * 16;

    const float* qp = qkv + h * HSZ;
    const float* kp = qkv + DD + h * HSZ;
    const float* vp = qkv + 2 * DD + h * HSZ;

    // load Q tile once
    for (int i = tid; i < 128 * 64; i += 256) {
        int r = i >> 6, d = i & 63;
        Qs[r * QS_S + d] = f2tf32(qp[(size_t)(q0 + r) * (3 * DD) + d]);
    }

    float O[8][4];
    #pragma unroll
    for (int nt = 0; nt < 8; nt++)
        #pragma unroll
        for (int i = 0; i < 4; i++) O[nt][i] = 0.f;
    float m0 = -1e30f, m1 = -1e30f, l0 = 0.f, l1 = 0.f;

    const int row0 = q0 + w16 + g;
    const int row1 = row0 + 8;
    const float SC = 0.18033688011112042f;   // (1/8) * log2(e)
    const int nkt = 2 * qb + 2;

    for (int kt = 0; kt < nkt; ++kt) {
        __syncthreads();
        for (int i = tid; i < 64 * 64; i += 256) {
            int r = i >> 6, d = i & 63;
            size_t gi = (size_t)(kt * 64 + r) * (3 * DD) + d;
            Ks[r * KS_S + d] = f2tf32(kp[gi]);
            Vs[r * VS_S + d] = f2tf32(vp[gi]);
        }
        __syncthreads();

        // ---- S = Q K^T : 8 n-chunks of 8 keys, 8 k-steps over d ----
        float s[8][4];
        #pragma unroll
        for (int nt = 0; nt < 8; nt++)
            #pragma unroll
            for (int i = 0; i < 4; i++) s[nt][i] = 0.f;

        #pragma unroll
        for (int kk = 0; kk < 8; ++kk) {
            const float* qr = &Qs[(w16 + g) * QS_S + kk * 8];
            uint32_t a0 = __float_as_uint(qr[tg]);
            uint32_t a1 = __float_as_uint(qr[8 * QS_S + tg]);
            uint32_t a2 = __float_as_uint(qr[tg + 4]);
            uint32_t a3 = __float_as_uint(qr[8 * QS_S + tg + 4]);
            #pragma unroll
            for (int nt = 0; nt < 8; ++nt) {
                const float* kr = &Ks[(nt * 8 + g) * KS_S + kk * 8];
                uint32_t b0 = __float_as_uint(kr[tg]);
                uint32_t b1 = __float_as_uint(kr[tg + 4]);
                mma_tf32(s[nt][0], s[nt][1], s[nt][2], s[nt][3],
                         a0, a1, a2, a3, b0, b1);
            }
        }

        // ---- softmax (log2 domain), causal mask ----
        float mb0 = -1e30f, mb1 = -1e30f;
        #pragma unroll
        for (int nt = 0; nt < 8; ++nt) {
            int c0 = kt * 64 + nt * 8 + 2 * tg;
            float z0 = (c0     > row0) ? -1e30f : s[nt][0] * SC;
            float z1 = (c0 + 1 > row0) ? -1e30f : s[nt][1] * SC;
            float z2 = (c0     > row1) ? -1e30f : s[nt][2] * SC;
            float z3 = (c0 + 1 > row1) ? -1e30f : s[nt][3] * SC;
            s[nt][0] = z0; s[nt][1] = z1; s[nt][2] = z2; s[nt][3] = z3;
            mb0 = fmaxf(mb0, fmaxf(z0, z1));
            mb1 = fmaxf(mb1, fmaxf(z2, z3));
        }
        mb0 = fmaxf(mb0, __shfl_xor_sync(0xffffffffu, mb0, 1));
        mb0 = fmaxf(mb0, __shfl_xor_sync(0xffffffffu, mb0, 2));
        mb1 = fmaxf(mb1, __shfl_xor_sync(0xffffffffu, mb1, 1));
        mb1 = fmaxf(mb1, __shfl_xor_sync(0xffffffffu, mb1, 2));

        float mn0 = fmaxf(m0, mb0), mn1 = fmaxf(m1, mb1);
        float al0 = fexp2(m0 - mn0), al1 = fexp2(m1 - mn1);
        m0 = mn0; m1 = mn1;

        float rs0 = 0.f, rs1 = 0.f;
        float* pw = &Ps[(w16 + g) * PS_S];
        #pragma unroll
        for (int nt = 0; nt < 8; ++nt) {
            float p0 = fexp2(s[nt][0] - mn0);
            float p1 = fexp2(s[nt][1] - mn0);
            float p2 = fexp2(s[nt][2] - mn1);
            float p3 = fexp2(s[nt][3] - mn1);
            rs0 += p0 + p1; rs1 += p2 + p3;
            pw[nt * 8 + 2 * tg]              = f2tf32(p0);
            pw[nt * 8 + 2 * tg + 1]          = f2tf32(p1);
            pw[8 * PS_S + nt * 8 + 2 * tg]     = f2tf32(p2);
            pw[8 * PS_S + nt * 8 + 2 * tg + 1] = f2tf32(p3);
        }
        rs0 += __shfl_xor_sync(0xffffffffu, rs0, 1);
        rs0 += __shfl_xor_sync(0xffffffffu, rs0, 2);
        rs1 += __shfl_xor_sync(0xffffffffu, rs1, 1);
        rs1 += __shfl_xor_sync(0xffffffffu, rs1, 2);
        l0 = l0 * al0 + rs0;
        l1 = l1 * al1 + rs1;

        #pragma unroll
        for (int nt = 0; nt < 8; ++nt) {
            O[nt][0] *= al0; O[nt][1] *= al0;
            O[nt][2] *= al1; O[nt][3] *= al1;
        }
        __syncwarp();

        // ---- O += P V : 8 k-steps over keys, 8 n-chunks over d ----
        #pragma unroll
        for (int kk = 0; kk < 8; ++kk) {
            const float* pr = &Ps[(w16 + g) * PS_S + kk * 8];
            uint32_t a0 = __float_as_uint(pr[tg]);
            uint32_t a1 = __float_as_uint(pr[8 * PS_S + tg]);
            uint32_t a2 = __float_as_uint(pr[tg + 4]);
            uint32_t a3 = __float_as_uint(pr[8 * PS_S + tg + 4]);
            #pragma unroll
            for (int nt = 0; nt < 8; ++nt) {
                uint32_t b0 = __float_as_uint(Vs[(kk * 8 + tg) * VS_S + nt * 8 + g]);
                uint32_t b1 = __float_as_uint(Vs[(kk * 8 + tg + 4) * VS_S + nt * 8 + g]);
                mma_tf32(O[nt][0], O[nt][1], O[nt][2], O[nt][3],
                         a0, a1, a2, a3, b0, b1);
            }
        }
    }

    // ---- normalize + write ----
    float inv0 = 1.0f / l0, inv1 = 1.0f / l1;
    #pragma unroll
    for (int nt = 0; nt < 8; ++nt) {
        int c = h * HSZ + nt * 8 + 2 * tg;
        float2 o0 = make_float2(O[nt][0] * inv0, O[nt][1] * inv0);
        float2 o1 = make_float2(O[nt][2] * inv1, O[nt][3] * inv1);
        *reinterpret_cast<float2*>(out + (size_t)row0 * DD + c) = o0;
        *reinterpret_cast<float2*>(out + (size_t)row1 * DD + c) = o1;
    }
}

// ---------------- launch ----------------
extern "C" void kernel_launch(void* const* d_in, const int* in_sizes, int n_in,
                              void* d_out, int out_size)
{
    const float* x    = (const float*)d_in[0];
    const float* Wq   = (const float*)d_in[1];
    const float* Wk   = (const float*)d_in[2];
    const float* Wv   = (const float*)d_in[3];
    const float* Wo   = (const float*)d_in[4];
    const float* bo   = (const float*)d_in[5];
    const float* W1   = (const float*)d_in[6];
    const float* b1   = (const float*)d_in[7];
    const float* W2   = (const float*)d_in[8];
    const float* b2   = (const float*)d_in[9];
    const float* ln1s = (const float*)d_in[10];
    const float* ln1b = (const float*)d_in[11];
    const float* ln2s = (const float*)d_in[12];
    const float* ln2b = (const float*)d_in[13];
    float* out = (float*)d_out;

    float *h, *wp, *qkv, *att, *x2, *ff;
    cudaGetSymbolAddress((void**)&h,   g_h);
    cudaGetSymbolAddress((void**)&wp,  g_wpack);
    cudaGetSymbolAddress((void**)&qkv, g_qkv);
    cudaGetSymbolAddress((void**)&att, g_att);
    cudaGetSymbolAddress((void**)&x2,  g_x2);
    cudaGetSymbolAddress((void**)&ff,  g_ff);

    cudaFuncSetAttribute(flash_tc,
                         cudaFuncAttributeMaxDynamicSharedMemorySize, FA_SMEM);

    // 1. LN1
    ln_kernel<<<TT, 256>>>(x, ln1s, ln1b, h);
    // 2. pack QKV weights -> [D, 3D]
    pack_qkv<<<(DD * 3 * DD + 255) / 256, 256>>>(Wq, Wk, Wv, wp);
    // 3. QKV GEMM: [T,D] x [D,3D] -> [T,3D]
    tgemm<0><<<dim3(3 * DD / 128, TT / 128), 256>>>(TT, 3 * DD, DD, h, wp,
                                                    nullptr, nullptr, qkv);
    // 4. causal flash attention (tensor cores) -> [T,D]
    flash_tc<<<dim3(TT / 128, HH), 256, FA_SMEM>>>(qkv, att);
    // 5. output proj + bias + residual: x2 = x + att*Wo + bo
    tgemm<1><<<dim3(DD / 128, TT / 128), 256>>>(TT, DD, DD, att, Wo, bo, x, x2);
    // 6. LN2
    ln_kernel<<<TT, 256>>>(x2, ln2s, ln2b, h);
    // 7. FFN1: relu(h*W1 + b1)
    tgemm<2><<<dim3(DFF / 128, TT / 128), 256>>>(TT, DFF, DD, h, W1, b1,
                                                 nullptr, ff);
    // 8. FFN2: out = x2 + ff*W2 + b2
    tgemm<1><<<dim3(DD / 128, TT / 128), 256>>>(TT, DD, DFF, ff, W2, b2, x2, out);
}

// round 5
// speedup vs baseline: 3.5213x; 1.2984x over previous
#include <cuda_runtime.h>
#include <cstdint>

#define TT 2048
#define DD 1024
#define HH 16
#define HSZ 64
#define DFF 4096

// ---------------- scratch (no allocs allowed) ----------------
__device__ float g_h[TT * DD];            // LN output
__device__ float g_wqkvT[3 * DD * DD];    // QKV weights, [3D][D] K-major
__device__ float g_WoT[DD * DD];          // Wo^T  [D][D]
__device__ float g_W1T[DD * DFF];         // W1^T  [DFF][D]
__device__ float g_W2T[DFF * DD];         // W2^T  [D][DFF]
__device__ float g_qkv[TT * 3 * DD];      // QKV activations [T, 3D]
__device__ float g_att[TT * DD];          // attention output [T, D]
__device__ float g_x2[TT * DD];           // residual after attention
__device__ float g_ff[TT * DFF];          // FFN hidden

// ---------------- helpers ----------------
__device__ __forceinline__ uint32_t smem_u32(const void* p) {
    return (uint32_t)__cvta_generic_to_shared(p);
}
__device__ __forceinline__ float f2tf32(float x) {
    uint32_t r;
    asm("cvt.rna.tf32.f32 %0, %1;" : "=r"(r) : "f"(x));
    return __uint_as_float(r);
}
__device__ __forceinline__ uint32_t swz(uint32_t off) {   // SW128 swizzle
    return off ^ ((off >> 3) & 0x70);
}
__device__ __forceinline__ void mma_tf32(
    float& d0, float& d1, float& d2, float& d3,
    uint32_t a0, uint32_t a1, uint32_t a2, uint32_t a3,
    uint32_t b0, uint32_t b1)
{
    asm volatile(
        "mma.sync.aligned.m16n8k8.row.col.f32.tf32.tf32.f32 "
        "{%0,%1,%2,%3}, {%4,%5,%6,%7}, {%8,%9}, {%0,%1,%2,%3};\n"
        : "+f"(d0), "+f"(d1), "+f"(d2), "+f"(d3)
        : "r"(a0), "r"(a1), "r"(a2), "r"(a3), "r"(b0), "r"(b1));
}
__device__ __forceinline__ void ldmx4(
    uint32_t& r0, uint32_t& r1, uint32_t& r2, uint32_t& r3, uint32_t addr)
{
    asm volatile("ldmatrix.sync.aligned.m8n8.x4.shared.b16 {%0,%1,%2,%3}, [%4];"
                 : "=r"(r0), "=r"(r1), "=r"(r2), "=r"(r3) : "r"(addr));
}
__device__ __forceinline__ void cpasync16(uint32_t saddr, const void* gaddr) {
    asm volatile("cp.async.cg.shared.global [%0], [%1], 16;" :: "r"(saddr), "l"(gaddr));
}
#define CP_COMMIT() asm volatile("cp.async.commit_group;" ::: "memory")
#define CP_WAIT(n)  asm volatile("cp.async.wait_group %0;" :: "n"(n) : "memory")

// ---------------- LayerNorm: one block per row ----------------
__global__ __launch_bounds__(256) void ln_kernel(
    const float* __restrict__ x, const float* __restrict__ g,
    const float* __restrict__ b, float* __restrict__ y)
{
    int row = blockIdx.x;
    int tid = threadIdx.x;
    float4 v = reinterpret_cast<const float4*>(x + (size_t)row * DD)[tid];
    float s  = v.x + v.y + v.z + v.w;
    float ss = v.x * v.x + v.y * v.y + v.z * v.z + v.w * v.w;
    #pragma unroll
    for (int o = 16; o > 0; o >>= 1) {
        s  += __shfl_xor_sync(0xffffffffu, s, o);
        ss += __shfl_xor_sync(0xffffffffu, ss, o);
    }
    __shared__ float sb[8], ssb[8], stats[2];
    int wid = tid >> 5, lane = tid & 31;
    if (lane == 0) { sb[wid] = s; ssb[wid] = ss; }
    __syncthreads();
    if (tid == 0) {
        float a = 0.f, c = 0.f;
        #pragma unroll
        for (int i = 0; i < 8; i++) { a += sb[i]; c += ssb[i]; }
        float mean = a * (1.0f / DD);
        float var  = c * (1.0f / DD) - mean * mean;
        stats[0] = mean;
        stats[1] = rsqrtf(var + 1e-6f);
    }
    __syncthreads();
    float mean = stats[0], rstd = stats[1];
    float4 gg = reinterpret_cast<const float4*>(g)[tid];
    float4 bb = reinterpret_cast<const float4*>(b)[tid];
    float4 o;
    o.x = (v.x - mean) * rstd * gg.x + bb.x;
    o.y = (v.y - mean) * rstd * gg.y + bb.y;
    o.z = (v.z - mean) * rstd * gg.z + bb.z;
    o.w = (v.w - mean) * rstd * gg.w + bb.w;
    reinterpret_cast<float4*>(y + (size_t)row * DD)[tid] = o;
}

// ---------------- 32x32 tiled transpose: out[c][r] = in[r][c] ----------------
__global__ __launch_bounds__(256) void transpose32(
    const float* __restrict__ in, float* __restrict__ out, int R, int C,
    int inChunkStride, int outChunkStride)
{
    __shared__ float t[32][33];
    const float* ip = in + (size_t)blockIdx.z * inChunkStride;
    float* op = out + (size_t)blockIdx.z * outChunkStride;
    int bx = blockIdx.x * 32;
    int by = blockIdx.y * 32;
    int x = threadIdx.x, y = threadIdx.y;
    #pragma unroll
    for (int j = 0; j < 32; j += 8)
        t[y + j][x] = ip[(size_t)(by + y + j) * C + bx + x];
    __syncthreads();
    #pragma unroll
    for (int j = 0; j < 32; j += 8)
        op[(size_t)(bx + y + j) * R + by + x] = t[x][y + j];
}

// ---------------- tf32 mma.sync GEMM, cp.async 3-stage + ldmatrix ----------------
// C[M,N] = epi( A[M,K] row-major  x  Bt[N,K] K-major ^T )
// CTA 128x128, BK=32, 8 warps (2x4), warp tile 64x32.
// smem per stage: A 16KB + B 16KB (128B rows, SW128 swizzle). 3 stages = 96KB.
// EPI: 0 = none, 1 = +bias[col]+resid, 2 = relu(+bias[col])
#define TG_STAGE 32768
#define TG_SMEM  (3 * TG_STAGE)

template <int EPI>
__global__ __launch_bounds__(256, 1) void tg2(
    int M, int N, int K,
    const float* __restrict__ A, const float* __restrict__ Bt,
    const float* __restrict__ bias, const float* __restrict__ resid,
    float* __restrict__ C)
{
    extern __shared__ float dynsm[];
    const int tid  = threadIdx.x;
    const int warp = tid >> 5, lane = tid & 31;
    const int wm = warp & 1, wn = warp >> 1;
    const int g = lane >> 2, tg = lane & 3;
    const int brow = blockIdx.y, bcol = blockIdx.x;

    const uint32_t sbase = smem_u32(dynsm);
    const int r0 = tid >> 3;      // 0..31
    const int ck = tid & 7;       // 16B chunk 0..7
    const float* Ab = A  + (size_t)(brow * 128) * K + ck * 4;
    const float* Bb = Bt + (size_t)(bcol * 128) * K + ck * 4;
    const int KT = K >> 5;

    // precomputed ldmatrix lane offsets
    const int aRow = (lane & 7) + ((lane >> 3) & 1) * 8;   // row within 16
    const int aChk = (lane >> 4);                          // +0 or +1 chunk
    const int bRow = (lane & 7) + (lane >> 4) * 8;         // n within 16
    const int bChk = (lane >> 3) & 1;                      // +0 or +1 chunk

    float acc[4][4][4];
    #pragma unroll
    for (int mt = 0; mt < 4; mt++)
        #pragma unroll
        for (int nt = 0; nt < 4; nt++)
            #pragma unroll
            for (int i = 0; i < 4; i++) acc[mt][nt][i] = 0.f;

    // stage loader
    auto load_stage = [&](int kt, int s) {
        const uint32_t sA = sbase + s * TG_STAGE;
        const uint32_t sB = sA + 16384;
        const int k0 = kt * 32;
        #pragma unroll
        for (int j = 0; j < 4; ++j) {
            const int r = j * 32 + r0;
            const uint32_t off = swz((uint32_t)(r * 128 + ck * 16));
            cpasync16(sA + off, Ab + (size_t)r * K + k0);
            cpasync16(sB + off, Bb + (size_t)r * K + k0);
        }
        CP_COMMIT();
    };

    load_stage(0, 0);
    load_stage(1, 1);

    for (int kt = 0; kt < KT; ++kt) {
        if (kt + 1 < KT) CP_WAIT(1); else CP_WAIT(0);
        __syncthreads();
        if (kt + 2 < KT) load_stage(kt + 2, (kt + 2) % 3);

        const uint32_t sA = sbase + (kt % 3) * TG_STAGE;
        const uint32_t sB = sA + 16384;

        #pragma unroll
        for (int ks = 0; ks < 4; ++ks) {
            const int chunkA = ks * 2;   // k8 step -> base 16B chunk (0,2,4,6)
            uint32_t af[4][4];
            #pragma unroll
            for (int mt = 0; mt < 4; ++mt) {
                const int row = wm * 64 + mt * 16 + aRow;
                const uint32_t ad = sA + swz((uint32_t)(row * 128 + (chunkA + aChk) * 16));
                ldmx4(af[mt][0], af[mt][1], af[mt][2], af[mt][3], ad);
            }
            uint32_t bf[4][2];
            #pragma unroll
            for (int np = 0; np < 2; ++np) {
                const int nrow = wn * 32 + np * 16 + bRow;
                const uint32_t bd = sB + swz((uint32_t)(nrow * 128 + (chunkA + bChk) * 16));
                uint32_t t0, t1, t2, t3;
                ldmx4(t0, t1, t2, t3, bd);
                bf[np * 2][0] = t0;     bf[np * 2][1] = t1;
                bf[np * 2 + 1][0] = t2; bf[np * 2 + 1][1] = t3;
            }
            #pragma unroll
            for (int mt = 0; mt < 4; ++mt)
                #pragma unroll
                for (int nt = 0; nt < 4; ++nt)
                    mma_tf32(acc[mt][nt][0], acc[mt][nt][1],
                             acc[mt][nt][2], acc[mt][nt][3],
                             af[mt][0], af[mt][1], af[mt][2], af[mt][3],
                             bf[nt][0], bf[nt][1]);
        }
    }

    // ---------------- epilogue (regs -> global) ----------------
    #pragma unroll
    for (int mt = 0; mt < 4; mt++) {
        const int r0g = brow * 128 + wm * 64 + mt * 16 + g;
        const int r1g = r0g + 8;
        #pragma unroll
        for (int nt = 0; nt < 4; nt++) {
            const int c = bcol * 128 + wn * 32 + nt * 8 + tg * 2;
            float2 o0 = make_float2(acc[mt][nt][0], acc[mt][nt][1]);
            float2 o1 = make_float2(acc[mt][nt][2], acc[mt][nt][3]);
            if constexpr (EPI >= 1) {
                float2 bv = *reinterpret_cast<const float2*>(bias + c);
                o0.x += bv.x; o0.y += bv.y;
                o1.x += bv.x; o1.y += bv.y;
            }
            if constexpr (EPI == 1) {
                float2 rv0 = *reinterpret_cast<const float2*>(resid + (size_t)r0g * N + c);
                float2 rv1 = *reinterpret_cast<const float2*>(resid + (size_t)r1g * N + c);
                o0.x += rv0.x; o0.y += rv0.y;
                o1.x += rv1.x; o1.y += rv1.y;
            }
            if constexpr (EPI == 2) {
                o0.x = fmaxf(o0.x, 0.f); o0.y = fmaxf(o0.y, 0.f);
                o1.x = fmaxf(o1.x, 0.f); o1.y = fmaxf(o1.y, 0.f);
            }
            *reinterpret_cast<float2*>(C + (size_t)r0g * N + c) = o0;
            *reinterpret_cast<float2*>(C + (size_t)r1g * N + c) = o1;
        }
    }
}

// ---------------- fast exp2 (fma pipe) ----------------
__device__ __forceinline__ float fexp2(float x) {
    x = fmaxf(x, -120.f);
    float k  = __fadd_rn(x, 12582912.f);
    int   sc = __float_as_int(k) << 23;
    float f  = __fsub_rn(x, __fsub_rn(k, 12582912.f));
    float p  = 0.0013333558f;
    p = fmaf(p, f, 0.0096181291f);
    p = fmaf(p, f, 0.0555041087f);
    p = fmaf(p, f, 0.2402265070f);
    p = fmaf(p, f, 0.6931471806f);
    p = fmaf(p, f, 1.0f);
    return __int_as_float(__float_as_int(p) + sc);
}

// ---------------- tensor-core flash attention (unchanged from R3) ----------------
#define QS_S 68
#define KS_S 68
#define VS_S 72
#define PS_S 68
#define FA_SMEM ((128*QS_S + 64*KS_S + 64*VS_S + 128*PS_S) * 4)

__global__ __launch_bounds__(256, 2) void flash_tc(
    const float* __restrict__ qkv, float* __restrict__ out)
{
    extern __shared__ float sm[];
    float* Qs = sm;
    float* Ks = Qs + 128 * QS_S;
    float* Vs = Ks + 64 * KS_S;
    float* Ps = Vs + 64 * VS_S;

    const int tid  = threadIdx.x;
    const int warp = tid >> 5;
    const int lane = tid & 31;
    const int g    = lane >> 2;
    const int tg   = lane & 3;
    const int qb   = gridDim.x - 1 - blockIdx.x;
    const int h    = blockIdx.y;
    const int q0   = qb * 128;
    const int w16  = warp * 16;

    const float* qp = qkv + h * HSZ;
    const float* kp = qkv + DD + h * HSZ;
    const float* vp = qkv + 2 * DD + h * HSZ;

    for (int i = tid; i < 128 * 64; i += 256) {
        int r = i >> 6, d = i & 63;
        Qs[r * QS_S + d] = f2tf32(qp[(size_t)(q0 + r) * (3 * DD) + d]);
    }

    float O[8][4];
    #pragma unroll
    for (int nt = 0; nt < 8; nt++)
        #pragma unroll
        for (int i = 0; i < 4; i++) O[nt][i] = 0.f;
    float m0 = -1e30f, m1 = -1e30f, l0 = 0.f, l1 = 0.f;

    const int row0 = q0 + w16 + g;
    const int row1 = row0 + 8;
    const float SC = 0.18033688011112042f;
    const int nkt = 2 * qb + 2;

    for (int kt = 0; kt < nkt; ++kt) {
        __syncthreads();
        for (int i = tid; i < 64 * 64; i += 256) {
            int r = i >> 6, d = i & 63;
            size_t gi = (size_t)(kt * 64 + r) * (3 * DD) + d;
            Ks[r * KS_S + d] = f2tf32(kp[gi]);
            Vs[r * VS_S + d] = f2tf32(vp[gi]);
        }
        __syncthreads();

        float s[8][4];
        #pragma unroll
        for (int nt = 0; nt < 8; nt++)
            #pragma unroll
            for (int i = 0; i < 4; i++) s[nt][i] = 0.f;

        #pragma unroll
        for (int kk = 0; kk < 8; ++kk) {
            const float* qr = &Qs[(w16 + g) * QS_S + kk * 8];
            uint32_t a0 = __float_as_uint(qr[tg]);
            uint32_t a1 = __float_as_uint(qr[8 * QS_S + tg]);
            uint32_t a2 = __float_as_uint(qr[tg + 4]);
            uint32_t a3 = __float_as_uint(qr[8 * QS_S + tg + 4]);
            #pragma unroll
            for (int nt = 0; nt < 8; ++nt) {
                const float* kr = &Ks[(nt * 8 + g) * KS_S + kk * 8];
                uint32_t b0 = __float_as_uint(kr[tg]);
                uint32_t b1 = __float_as_uint(kr[tg + 4]);
                mma_tf32(s[nt][0], s[nt][1], s[nt][2], s[nt][3],
                         a0, a1, a2, a3, b0, b1);
            }
        }

        float mb0 = -1e30f, mb1 = -1e30f;
        #pragma unroll
        for (int nt = 0; nt < 8; ++nt) {
            int c0 = kt * 64 + nt * 8 + 2 * tg;
            float z0 = (c0     > row0) ? -1e30f : s[nt][0] * SC;
            float z1 = (c0 + 1 > row0) ? -1e30f : s[nt][1] * SC;
            float z2 = (c0     > row1) ? -1e30f : s[nt][2] * SC;
            float z3 = (c0 + 1 > row1) ? -1e30f : s[nt][3] * SC;
            s[nt][0] = z0; s[nt][1] = z1; s[nt][2] = z2; s[nt][3] = z3;
            mb0 = fmaxf(mb0, fmaxf(z0, z1));
            mb1 = fmaxf(mb1, fmaxf(z2, z3));
        }
        mb0 = fmaxf(mb0, __shfl_xor_sync(0xffffffffu, mb0, 1));
        mb0 = fmaxf(mb0, __shfl_xor_sync(0xffffffffu, mb0, 2));
        mb1 = fmaxf(mb1, __shfl_xor_sync(0xffffffffu, mb1, 1));
        mb1 = fmaxf(mb1, __shfl_xor_sync(0xffffffffu, mb1, 2));

        float mn0 = fmaxf(m0, mb0), mn1 = fmaxf(m1, mb1);
        float al0 = fexp2(m0 - mn0), al1 = fexp2(m1 - mn1);
        m0 = mn0; m1 = mn1;

        float rs0 = 0.f, rs1 = 0.f;
        float* pw = &Ps[(w16 + g) * PS_S];
        #pragma unroll
        for (int nt = 0; nt < 8; ++nt) {
            float p0 = fexp2(s[nt][0] - mn0);
            float p1 = fexp2(s[nt][1] - mn0);
            float p2 = fexp2(s[nt][2] - mn1);
            float p3 = fexp2(s[nt][3] - mn1);
            rs0 += p0 + p1; rs1 += p2 + p3;
            pw[nt * 8 + 2 * tg]              = f2tf32(p0);
            pw[nt * 8 + 2 * tg + 1]          = f2tf32(p1);
            pw[8 * PS_S + nt * 8 + 2 * tg]     = f2tf32(p2);
            pw[8 * PS_S + nt * 8 + 2 * tg + 1] = f2tf32(p3);
        }
        rs0 += __shfl_xor_sync(0xffffffffu, rs0, 1);
        rs0 += __shfl_xor_sync(0xffffffffu, rs0, 2);
        rs1 += __shfl_xor_sync(0xffffffffu, rs1, 1);
        rs1 += __shfl_xor_sync(0xffffffffu, rs1, 2);
        l0 = l0 * al0 + rs0;
        l1 = l1 * al1 + rs1;

        #pragma unroll
        for (int nt = 0; nt < 8; ++nt) {
            O[nt][0] *= al0; O[nt][1] *= al0;
            O[nt][2] *= al1; O[nt][3] *= al1;
        }
        __syncwarp();

        #pragma unroll
        for (int kk = 0; kk < 8; ++kk) {
            const float* pr = &Ps[(w16 + g) * PS_S + kk * 8];
            uint32_t a0 = __float_as_uint(pr[tg]);
            uint32_t a1 = __float_as_uint(pr[8 * PS_S + tg]);
            uint32_t a2 = __float_as_uint(pr[tg + 4]);
            uint32_t a3 = __float_as_uint(pr[8 * PS_S + tg + 4]);
            #pragma unroll
            for (int nt = 0; nt < 8; ++nt) {
                uint32_t b0 = __float_as_uint(Vs[(kk * 8 + tg) * VS_S + nt * 8 + g]);
                uint32_t b1 = __float_as_uint(Vs[(kk * 8 + tg + 4) * VS_S + nt * 8 + g]);
                mma_tf32(O[nt][0], O[nt][1], O[nt][2], O[nt][3],
                         a0, a1, a2, a3, b0, b1);
            }
        }
    }

    float inv0 = 1.0f / l0, inv1 = 1.0f / l1;
    #pragma unroll
    for (int nt = 0; nt < 8; ++nt) {
        int c = h * HSZ + nt * 8 + 2 * tg;
        float2 o0 = make_float2(O[nt][0] * inv0, O[nt][1] * inv0);
        float2 o1 = make_float2(O[nt][2] * inv1, O[nt][3] * inv1);
        *reinterpret_cast<float2*>(out + (size_t)row0 * DD + c) = o0;
        *reinterpret_cast<float2*>(out + (size_t)row1 * DD + c) = o1;
    }
}

// ---------------- launch ----------------
extern "C" void kernel_launch(void* const* d_in, const int* in_sizes, int n_in,
                              void* d_out, int out_size)
{
    const float* x    = (const float*)d_in[0];
    const float* Wq   = (const float*)d_in[1];
    const float* Wk   = (const float*)d_in[2];
    const float* Wv   = (const float*)d_in[3];
    const float* Wo   = (const float*)d_in[4];
    const float* bo   = (const float*)d_in[5];
    const float* W1   = (const float*)d_in[6];
    const float* b1   = (const float*)d_in[7];
    const float* W2   = (const float*)d_in[8];
    const float* b2   = (const float*)d_in[9];
    const float* ln1s = (const float*)d_in[10];
    const float* ln1b = (const float*)d_in[11];
    const float* ln2s = (const float*)d_in[12];
    const float* ln2b = (const float*)d_in[13];
    float* out = (float*)d_out;

    float *h, *wqkvT, *woT, *w1T, *w2T, *qkv, *att, *x2, *ff;
    cudaGetSymbolAddress((void**)&h,     g_h);
    cudaGetSymbolAddress((void**)&wqkvT, g_wqkvT);
    cudaGetSymbolAddress((void**)&woT,   g_WoT);
    cudaGetSymbolAddress((void**)&w1T,   g_W1T);
    cudaGetSymbolAddress((void**)&w2T,   g_W2T);
    cudaGetSymbolAddress((void**)&qkv,   g_qkv);
    cudaGetSymbolAddress((void**)&att,   g_att);
    cudaGetSymbolAddress((void**)&x2,    g_x2);
    cudaGetSymbolAddress((void**)&ff,    g_ff);

    cudaFuncSetAttribute(flash_tc, cudaFuncAttributeMaxDynamicSharedMemorySize, FA_SMEM);
    cudaFuncSetAttribute(tg2<0>, cudaFuncAttributeMaxDynamicSharedMemorySize, TG_SMEM);
    cudaFuncSetAttribute(tg2<1>, cudaFuncAttributeMaxDynamicSharedMemorySize, TG_SMEM);
    cudaFuncSetAttribute(tg2<2>, cudaFuncAttributeMaxDynamicSharedMemorySize, TG_SMEM);

    dim3 tb(32, 8);

    // 1. LN1
    ln_kernel<<<TT, 256>>>(x, ln1s, ln1b, h);
    // 2. weight transposes -> K-major B operands
    transpose32<<<dim3(2, 32, 16), tb>>>(Wq, wqkvT,           DD, HSZ, DD*HSZ, HSZ*DD);
    transpose32<<<dim3(2, 32, 16), tb>>>(Wk, wqkvT + DD*DD,   DD, HSZ, DD*HSZ, HSZ*DD);
    transpose32<<<dim3(2, 32, 16), tb>>>(Wv, wqkvT + 2*DD*DD, DD, HSZ, DD*HSZ, HSZ*DD);
    transpose32<<<dim3(32, 32, 1),  tb>>>(Wo, woT, DD, DD, 0, 0);
    transpose32<<<dim3(128, 32, 1), tb>>>(W1, w1T, DD, DFF, 0, 0);
    transpose32<<<dim3(32, 128, 1), tb>>>(W2, w2T, DFF, DD, 0, 0);
    // 3. QKV GEMM: [T,D] x [D,3D] -> [T,3D]
    tg2<0><<<dim3(3 * DD / 128, TT / 128), 256, TG_SMEM>>>(
        TT, 3 * DD, DD, h, wqkvT, nullptr, nullptr, qkv);
    // 4. causal flash attention -> [T,D]
    flash_tc<<<dim3(TT / 128, HH), 256, FA_SMEM>>>(qkv, att);
    // 5. output proj + bias + residual
    tg2<1><<<dim3(DD / 128, TT / 128), 256, TG_SMEM>>>(
        TT, DD, DD, att, woT, bo, x, x2);
    // 6. LN2
    ln_kernel<<<TT, 256>>>(x2, ln2s, ln2b, h);
    // 7. FFN1
    tg2<2><<<dim3(DFF / 128, TT / 128), 256, TG_SMEM>>>(
        TT, DFF, DD, h, w1T, b1, nullptr, ff);
    // 8. FFN2
    tg2<1><<<dim3(DD / 128, TT / 128), 256, TG_SMEM>>>(
        TT, DD, DFF, ff, w2T, b2, x2, out);
}